// round 14
// baseline (speedup 1.0000x reference)
#include <cuda_runtime.h>
#include <cstdint>
#include <cstddef>

#define NA 2048
#define HH 128
#define NE 32768
#define RR 32
#define NH (NA*HH)
#define CUT 4.5f

// ---------------- scratch (static device globals; no allocations) ----------------
__device__ float g_ea0[NE*384];         // edge MLP output layer 0, [e][3][128]
__device__ float g_ea1[NE*384];         // edge MLP output layer 1
__device__ float g_Xn[NH*9];
__device__ float g_cA[9*NH];
__device__ float g_cM[9*NH];
__device__ float g_c2[9*NH];
__device__ float g_dXc[9*NH];
__device__ unsigned g_W1f[2*8*2*32*8];      // bf16 hi/lo fragment images
__device__ unsigned g_W2f[2*16*8*32*8];
__device__ unsigned g_W3f[2*24*16*32*8];    // W3 output-permuted: o' = c*128+h
__device__ unsigned g_WmF[12*8*8*32*8];     // Wt fragment images for k_mix_mma
__device__ int   g_cnt[NA];
__device__ int   g_cur[NA];
__device__ int   g_row[NA+1];
__device__ int   g_eord[NE];

typedef unsigned long long u64;
typedef unsigned u32;

// ---------------- generic helpers ----------------
__device__ __forceinline__ float siluf(float x){ return x / (1.f + __expf(-x)); }

__device__ __forceinline__ void split_pair(float x, float y, u32& hi, u32& lo){
    u32 ux=__float_as_uint(x), uy=__float_as_uint(y);
    float rx = x - __uint_as_float(ux&0xFFFF0000u);
    float ry = y - __uint_as_float(uy&0xFFFF0000u);
    hi = (ux>>16) | (uy & 0xFFFF0000u);
    lo = (__float_as_uint(rx)>>16) | (__float_as_uint(ry)&0xFFFF0000u);
}

__device__ __forceinline__ int wpos(int w){ return 2*(w&3) + (w>>2); }

__device__ __forceinline__ void st_hl(u32* hiP, u32* loP, int padw, int e, int o, float v){
    u32 u = __float_as_uint(v);
    float r = v - __uint_as_float(u&0xFFFF0000u);
    int w = (o&15)>>1;
    int idx = e*padw + (o>>4)*8 + wpos(w);
    unsigned short* hp = (unsigned short*)(hiP+idx) + (o&1);
    unsigned short* lp = (unsigned short*)(loP+idx) + (o&1);
    *hp = (unsigned short)(u>>16);
    *lp = (unsigned short)(__float_as_uint(r)>>16);
}

__device__ __forceinline__ void mma16(float* d, const u32* a, const u32* b){
    asm volatile("mma.sync.aligned.m16n8k16.row.col.f32.bf16.bf16.f32 "
        "{%0,%1,%2,%3}, {%4,%5,%6,%7}, {%8,%9}, {%0,%1,%2,%3};"
        : "+f"(d[0]),"+f"(d[1]),"+f"(d[2]),"+f"(d[3])
        : "r"(a[0]),"r"(a[1]),"r"(a[2]),"r"(a[3]), "r"(b[0]),"r"(b[1]));
}

struct WF { uint4 h, l; };
__device__ __forceinline__ void ldwf(const uint4* __restrict__ W, int idx, WF& w){
    w.h = W[idx*2]; w.l = W[idx*2+1];
}

template<int M>
__device__ __forceinline__ void do_mma16_M(float (&d)[M][8][4], const WF (&w)[M],
                                           const u32* __restrict__ hiP,
                                           const u32* __restrict__ loP,
                                           int padw, int ebase, int kc8, int g, int t){
    #pragma unroll
    for(int nt=0;nt<8;nt++){
        int e = ebase + nt*8 + g;
        uint2 bh = *(const uint2*)&hiP[e*padw + kc8 + 2*t];
        uint2 bl = *(const uint2*)&loP[e*padw + kc8 + 2*t];
        #pragma unroll
        for(int m=0;m<M;m++){
            const u32* ah = (const u32*)&w[m].h;
            const u32* al = (const u32*)&w[m].l;
            mma16(d[m][nt],ah,(const u32*)&bh);
            mma16(d[m][nt],ah,(const u32*)&bl);
            mma16(d[m][nt],al,(const u32*)&bh);
        }
    }
}

// compact basis: {i0, a01, a02, a12, s00, s01, s02, s11, s12}
__device__ __forceinline__ void tocompact(const float* t, float s, float* c){
    float i0 = (t[0]+t[4]+t[8])*(1.f/3.f);
    c[0] = i0*s;
    c[1] = 0.5f*(t[1]-t[3])*s;
    c[2] = 0.5f*(t[2]-t[6])*s;
    c[3] = 0.5f*(t[5]-t[7])*s;
    c[4] = (t[0]-i0)*s;
    c[5] = 0.5f*(t[1]+t[3])*s;
    c[6] = 0.5f*(t[2]+t[6])*s;
    c[7] = (t[4]-i0)*s;
    c[8] = 0.5f*(t[5]+t[7])*s;
}
__device__ __forceinline__ void rec(const float* c, float* t){
    float i0=c[0], a01=c[1], a02=c[2], a12=c[3];
    float s00=c[4], s01=c[5], s02=c[6], s11=c[7], s12=c[8];
    t[0]=i0+s00;  t[1]=a01+s01; t[2]=a02+s02;
    t[3]=s01-a01; t[4]=i0+s11;  t[5]=a12+s12;
    t[6]=s02-a02; t[7]=s12-a12; t[8]=i0-s00-s11;
}
__device__ __forceinline__ void mmadd(const float* A, const float* B, float* C){
    #pragma unroll
    for(int i=0;i<3;i++){
        #pragma unroll
        for(int j=0;j<3;j++)
            C[i*3+j] += A[i*3+0]*B[0*3+j] + A[i*3+1]*B[1*3+j] + A[i*3+2]*B[2*3+j];
    }
}

// ---------------- weight prep: bf16 hi/lo fragment images (+cnt zero) ----------
__device__ __forceinline__ void packw(const float* __restrict__ W, int stride,
                                      int r, int k, u32& hi, u32& lo){
    float w0=W[r*stride+k], w1=W[r*stride+k+1];
    u32 u0=__float_as_uint(w0);
    float r0=w0-__uint_as_float(u0&0xFFFF0000u);
    float r1=w1-__uint_as_float(__float_as_uint(w1)&0xFFFF0000u);
    hi = (u0>>16) | (__float_as_uint(w1)&0xFFFF0000u);
    lo = (__float_as_uint(r0)>>16) | (__float_as_uint(r1)&0xFFFF0000u);
}

__global__ void k_prep_w(const float* __restrict__ Ws1, const float* __restrict__ Ws2,
                         const float* __restrict__ Ws3, const float* __restrict__ Wt){
    int stride = gridDim.x*blockDim.x;
    int t0 = blockIdx.x*blockDim.x + threadIdx.x;
    if(t0 < NA){ g_cnt[t0]=0; g_cur[t0]=0; }
    for(int i=t0;i<2*8*2*32;i+=stride){
        int l=i>>9, r=i&511, ot=r>>6, r2=r&63, kc=r2>>5, lane=r2&31;
        int g=lane>>2, t=lane&3, o0=ot*16, kb=kc*16;
        const float* W = Ws1 + (size_t)l*128*32;
        u32 f[8];
        packw(W,32,o0+g,  kb+2*t,  f[0],f[4]);
        packw(W,32,o0+g+8,kb+2*t,  f[1],f[5]);
        packw(W,32,o0+g,  kb+2*t+8,f[2],f[6]);
        packw(W,32,o0+g+8,kb+2*t+8,f[3],f[7]);
        u32* dst = g_W1f + ((size_t)l*512 + (ot*2+kc)*32 + lane)*8;
        #pragma unroll
        for(int j=0;j<8;j++) dst[j]=f[j];
    }
    for(int i=t0;i<2*16*8*32;i+=stride){
        int l=i>>12, r=i&4095, ot=r>>8, r2=r&255, kc=r2>>5, lane=r2&31;
        int g=lane>>2, t=lane&3, o0=ot*16, kb=kc*16;
        const float* W = Ws2 + (size_t)l*256*128;
        u32 f[8];
        packw(W,128,o0+g,  kb+2*t,  f[0],f[4]);
        packw(W,128,o0+g+8,kb+2*t,  f[1],f[5]);
        packw(W,128,o0+g,  kb+2*t+8,f[2],f[6]);
        packw(W,128,o0+g+8,kb+2*t+8,f[3],f[7]);
        u32* dst = g_W2f + ((size_t)l*4096 + (ot*8+kc)*32 + lane)*8;
        #pragma unroll
        for(int j=0;j<8;j++) dst[j]=f[j];
    }
    for(int i=t0;i<2*24*16*32;i+=stride){
        int l=i/12288, r=i%12288, ot=r>>9, r2=r&511, kc=r2>>5, lane=r2&31;
        int g=lane>>2, t=lane&3, o0=ot*16, kb=kc*16;
        const float* W = Ws3 + (size_t)l*384*256;
        int rows[2] = { o0+g, o0+g+8 };
        u32 f[8];
        #pragma unroll
        for(int rr=0;rr<2;rr++){
            int op = rows[rr];
            int j = (op&127)*3 + (op>>7);
            packw(W,256,j,kb+2*t,  f[rr],  f[rr+4]);
            packw(W,256,j,kb+2*t+8,f[rr+2],f[rr+6]);
        }
        u32* dst = g_W3f + ((size_t)l*12288 + (ot*16+kc)*32 + lane)*8;
        #pragma unroll
        for(int j=0;j<8;j++) dst[j]=f[j];
    }
    for(int i=t0;i<12*8*8*32;i+=stride){
        int lm=i/2048, r=i%2048, ot=r>>8, r2=r&255, kc=r2>>5, lane=r2&31;
        int g=lane>>2, t=lane&3, o0=ot*16, kb=kc*16;
        const float* W = Wt + (size_t)lm*16384;
        u32 f[8];
        packw(W,128,o0+g,  kb+2*t,  f[0],f[4]);
        packw(W,128,o0+g+8,kb+2*t,  f[1],f[5]);
        packw(W,128,o0+g,  kb+2*t+8,f[2],f[6]);
        packw(W,128,o0+g+8,kb+2*t+8,f[3],f[7]);
        u32* dst = g_WmF + ((size_t)(lm*64 + ot*8+kc)*32 + lane)*8;
        #pragma unroll
        for(int j=0;j<8;j++) dst[j]=f[j];
    }
}

// ---------------- CSR build ----------------
__global__ void k_count(const int* __restrict__ ei){
    int e = blockIdx.x*blockDim.x + threadIdx.x;
    if(e<NE) atomicAdd(&g_cnt[ei[e]], 1);
}
__global__ void k_scan(){
    __shared__ int sh[1024];
    int t = threadIdx.x;
    int v0 = g_cnt[2*t], v1 = g_cnt[2*t+1];
    int s = v0+v1;
    sh[t]=s; __syncthreads();
    #pragma unroll
    for(int off=1; off<1024; off<<=1){
        int x = (t>=off)? sh[t-off] : 0;
        __syncthreads();
        sh[t] += x;
        __syncthreads();
    }
    int incl = sh[t];
    int excl = incl - s;
    g_row[2*t]   = excl;
    g_row[2*t+1] = excl + v0;
    if(t==1023) g_row[2048]=incl;
}
__global__ void k_place(const int* __restrict__ ei){
    int e = blockIdx.x*blockDim.x + threadIdx.x;
    if(e<NE){
        int s = ei[e];
        int p = atomicAdd(&g_cur[s],1);
        g_eord[g_row[s]+p] = e;
    }
}

// ---------------- node prep ----------------
__global__ void k_node_prep(const float* __restrict__ Xin){
    int idx = blockIdx.x*blockDim.x + threadIdx.x;
    if(idx>=NH) return;
    float t[9]; float nrm=0.f;
    #pragma unroll
    for(int r=0;r<9;r++){ t[r]=Xin[(size_t)idx*9+r]; nrm += t[r]*t[r]; }
    float inv = 1.f/(nrm+1.f);
    #pragma unroll
    for(int r=0;r<9;r++){ t[r]*=inv; g_Xn[(size_t)idx*9+r]=t[r]; }
    float c[9]; tocompact(t,1.f,c);
    #pragma unroll
    for(int d=0;d<9;d++) g_cA[d*NH+idx]=c[d];
}

// ---------------- channel mix on tensor cores (bf16 split mma) ----------------
#define MIX_PADW 72
#define MIX_SMEMW (2*128*MIX_PADW)

__global__ void __launch_bounds__(512)
k_mix_mma(int which, int wbase){
    extern __shared__ u32 smu[];
    u32* inh = smu;
    u32* inl = smu + 128*MIX_PADW;
    const float* in  = which ? g_c2  : g_cA;
    float*       out = which ? g_dXc : g_cM;
    int d = blockIdx.y;
    int m = (d==0)?0:((d<4)?1:2);
    int lm = wbase + m;
    int nblk = blockIdx.x*128;
    int tid = threadIdx.x;
    int warp = tid>>5, lane = tid&31;
    int g = lane>>2, t = lane&3;
    int hw = warp>>1;
    int ebase = (warp&1)*64;

    const float* src = in + (size_t)d*NH + (size_t)nblk*HH;
    for(int i=tid;i<4096;i+=512){
        int e=i>>5, k4=(i&31)<<2;
        float4 v = *(const float4*)&src[e*128 + k4];
        int kc = k4>>4;
        int lw = (k4&15)>>1;
        u32 hi0,lo0,hi1,lo1;
        split_pair(v.x,v.y,hi0,lo0);
        split_pair(v.z,v.w,hi1,lo1);
        int base = e*MIX_PADW + kc*8;
        inh[base + wpos(lw)]   = hi0;
        inh[base + wpos(lw+1)] = hi1;
        inl[base + wpos(lw)]   = lo0;
        inl[base + wpos(lw+1)] = lo1;
    }
    __syncthreads();

    const uint4* Wm = (const uint4*)(g_WmF + (size_t)lm*64*32*8);
    float dacc[1][8][4];
    #pragma unroll
    for(int nt=0;nt<8;nt++){ dacc[0][nt][0]=dacc[0][nt][1]=dacc[0][nt][2]=dacc[0][nt][3]=0.f; }
    WF wa[1], wb[1];
    ldwf(Wm, (hw*8+0)*32+lane, wa[0]);
    #pragma unroll 1
    for(int kc=0;kc<8;kc+=2){
        ldwf(Wm, (hw*8+kc+1)*32+lane, wb[0]);
        do_mma16_M<1>(dacc, wa, inh, inl, MIX_PADW, ebase, kc*8, g, t);
        if(kc+2<8) ldwf(Wm, (hw*8+kc+2)*32+lane, wa[0]);
        do_mma16_M<1>(dacc, wb, inh, inl, MIX_PADW, ebase, (kc+1)*8, g, t);
    }
    float* outp = out + (size_t)d*NH + (size_t)nblk*HH;
    int oA = hw*16 + g, oB = oA + 8;
    #pragma unroll
    for(int nt=0;nt<8;nt++){
        int e0 = ebase + nt*8 + 2*t;
        outp[e0*128 + oA]     = dacc[0][nt][0];
        outp[(e0+1)*128 + oA] = dacc[0][nt][1];
        outp[e0*128 + oB]     = dacc[0][nt][2];
        outp[(e0+1)*128 + oB] = dacc[0][nt][3];
    }
}

// ---------------- edge MLP: bf16 split mma, hi/lo planes, m-tile B-reuse ------
#define A_PADW  40
#define H1_PADW 72
#define H2_PADW 136
#define MLP_SMEMW (128 + 2*128*H1_PADW + 2*128*H2_PADW)

__global__ void __launch_bounds__(512,1)
k_mlp_mma(const float* __restrict__ attr, const float* __restrict__ ewt,
          const float* __restrict__ b1, const float* __restrict__ b2,
          const float* __restrict__ b3raw, int l, float* __restrict__ eaOut){
    extern __shared__ u32 smu[];
    float* cv = (float*)smu;
    u32* h1h = smu + 128;
    u32* h1l = h1h + 128*H1_PADW;
    u32* h2h = h1l + 128*H1_PADW;
    u32* h2l = h2h + 128*H2_PADW;
    u32* aah = h2h;
    u32* aal = h2l;
    int tid = threadIdx.x;
    int warp = tid>>5, lane = tid&31;
    int g = lane>>2, t = lane&3;
    int hw = warp>>1;
    int ebase = (warp&1)*64;
    int eblk = blockIdx.x*128;

    const uint4* W1 = (const uint4*)(g_W1f + (size_t)l*4096);
    const uint4* W2 = (const uint4*)(g_W2f + (size_t)l*32768);
    const uint4* W3 = (const uint4*)(g_W3f + (size_t)l*98304);

    for(int i=tid;i<1024;i+=512){
        int e=i>>3, k4=(i&7)<<2;
        float4 v = *(const float4*)&attr[(size_t)(eblk+e)*32 + k4];
        int kc = k4>>4;
        int lw = (k4&15)>>1;
        u32 hi0,lo0,hi1,lo1;
        split_pair(v.x,v.y,hi0,lo0);
        split_pair(v.z,v.w,hi1,lo1);
        int base = e*A_PADW + kc*8;
        aah[base + wpos(lw)]   = hi0;
        aah[base + wpos(lw+1)] = hi1;
        aal[base + wpos(lw)]   = lo0;
        aal[base + wpos(lw+1)] = lo1;
    }
    if(tid<128){
        float wv = ewt[eblk+tid];
        cv[tid] = (wv < CUT) ? 0.5f*(cosf(wv*(3.14159265358979f/CUT))+1.f) : 0.f;
    }
    __syncthreads();

    // ---- stage 1 ----
    {
        float d[1][8][4];
        #pragma unroll
        for(int nt=0;nt<8;nt++){ d[0][nt][0]=d[0][nt][1]=d[0][nt][2]=d[0][nt][3]=0.f; }
        WF wa[1], wb[1];
        ldwf(W1, (hw*2+0)*32+lane, wa[0]);
        ldwf(W1, (hw*2+1)*32+lane, wb[0]);
        do_mma16_M<1>(d, wa, aah, aal, A_PADW, ebase, 0, g, t);
        do_mma16_M<1>(d, wb, aah, aal, A_PADW, ebase, 8, g, t);
        int o = hw*16;
        float bA=b1[o+g], bB=b1[o+g+8];
        #pragma unroll
        for(int nt=0;nt<8;nt++){
            int e = ebase + nt*8 + 2*t;
            st_hl(h1h,h1l,H1_PADW,e,  o+g,  siluf(d[0][nt][0]+bA));
            st_hl(h1h,h1l,H1_PADW,e+1,o+g,  siluf(d[0][nt][1]+bA));
            st_hl(h1h,h1l,H1_PADW,e,  o+g+8,siluf(d[0][nt][2]+bB));
            st_hl(h1h,h1l,H1_PADW,e+1,o+g+8,siluf(d[0][nt][3]+bB));
        }
    }
    __syncthreads();

    // ---- stage 2: single pass, 2 m-tiles ----
    {
        float d[2][8][4];
        #pragma unroll
        for(int m=0;m<2;m++)
            #pragma unroll
            for(int nt=0;nt<8;nt++){ d[m][nt][0]=d[m][nt][1]=d[m][nt][2]=d[m][nt][3]=0.f; }
        WF wa[2], wb[2];
        #pragma unroll
        for(int m=0;m<2;m++) ldwf(W2, ((hw*2+m)*8+0)*32+lane, wa[m]);
        #pragma unroll 1
        for(int kc=0;kc<8;kc+=2){
            #pragma unroll
            for(int m=0;m<2;m++) ldwf(W2, ((hw*2+m)*8+kc+1)*32+lane, wb[m]);
            do_mma16_M<2>(d, wa, h1h, h1l, H1_PADW, ebase, kc*8, g, t);
            if(kc+2<8){
                #pragma unroll
                for(int m=0;m<2;m++) ldwf(W2, ((hw*2+m)*8+kc+2)*32+lane, wa[m]);
            }
            do_mma16_M<2>(d, wb, h1h, h1l, H1_PADW, ebase, (kc+1)*8, g, t);
        }
        #pragma unroll
        for(int m=0;m<2;m++){
            int oo = hw*32 + m*16;
            float bA=b2[oo+g], bB=b2[oo+g+8];
            #pragma unroll
            for(int nt=0;nt<8;nt++){
                int e = ebase + nt*8 + 2*t;
                st_hl(h2h,h2l,H2_PADW,e,  oo+g,  siluf(d[m][nt][0]+bA));
                st_hl(h2h,h2l,H2_PADW,e+1,oo+g,  siluf(d[m][nt][1]+bA));
                st_hl(h2h,h2l,H2_PADW,e,  oo+g+8,siluf(d[m][nt][2]+bB));
                st_hl(h2h,h2l,H2_PADW,e+1,oo+g+8,siluf(d[m][nt][3]+bB));
            }
        }
    }
    __syncthreads();

    // ---- stage 3: pass A = 2 m-tiles, pass B = 1 m-tile ----
    {
        float d[2][8][4];
        #pragma unroll
        for(int m=0;m<2;m++)
            #pragma unroll
            for(int nt=0;nt<8;nt++){ d[m][nt][0]=d[m][nt][1]=d[m][nt][2]=d[m][nt][3]=0.f; }
        WF wa[2], wb[2];
        #pragma unroll
        for(int m=0;m<2;m++) ldwf(W3, ((hw*3+m)*16+0)*32+lane, wa[m]);
        #pragma unroll 1
        for(int kc=0;kc<16;kc+=2){
            #pragma unroll
            for(int m=0;m<2;m++) ldwf(W3, ((hw*3+m)*16+kc+1)*32+lane, wb[m]);
            do_mma16_M<2>(d, wa, h2h, h2l, H2_PADW, ebase, kc*8, g, t);
            if(kc+2<16){
                #pragma unroll
                for(int m=0;m<2;m++) ldwf(W3, ((hw*3+m)*16+kc+2)*32+lane, wa[m]);
            }
            do_mma16_M<2>(d, wb, h2h, h2l, H2_PADW, ebase, (kc+1)*8, g, t);
        }
        #pragma unroll
        for(int m=0;m<2;m++){
            int oA = hw*48 + m*16 + g, oB = oA + 8;
            float bA = b3raw[(oA&127)*3 + (oA>>7)];
            float bB = b3raw[(oB&127)*3 + (oB>>7)];
            #pragma unroll
            for(int nt=0;nt<8;nt++){
                int e0 = ebase + nt*8 + 2*t;
                float c0 = cv[e0], c1 = cv[e0+1];
                float* ep0 = eaOut + (size_t)(eblk+e0)*384;
                float* ep1 = eaOut + (size_t)(eblk+e0+1)*384;
                ep0[oA] = siluf(d[m][nt][0]+bA)*c0;
                ep1[oA] = siluf(d[m][nt][1]+bA)*c1;
                ep0[oB] = siluf(d[m][nt][2]+bB)*c0;
                ep1[oB] = siluf(d[m][nt][3]+bB)*c1;
            }
        }
    }
    {
        float d[1][8][4];
        #pragma unroll
        for(int nt=0;nt<8;nt++){ d[0][nt][0]=d[0][nt][1]=d[0][nt][2]=d[0][nt][3]=0.f; }
        WF wa[1], wb[1];
        ldwf(W3, ((hw*3+2)*16+0)*32+lane, wa[0]);
        #pragma unroll 1
        for(int kc=0;kc<16;kc+=2){
            ldwf(W3, ((hw*3+2)*16+kc+1)*32+lane, wb[0]);
            do_mma16_M<1>(d, wa, h2h, h2l, H2_PADW, ebase, kc*8, g, t);
            if(kc+2<16) ldwf(W3, ((hw*3+2)*16+kc+2)*32+lane, wa[0]);
            do_mma16_M<1>(d, wb, h2h, h2l, H2_PADW, ebase, (kc+1)*8, g, t);
        }
        int oA = hw*48 + 2*16 + g, oB = oA + 8;
        float bA = b3raw[(oA&127)*3 + (oA>>7)];
        float bB = b3raw[(oB&127)*3 + (oB>>7)];
        #pragma unroll
        for(int nt=0;nt<8;nt++){
            int e0 = ebase + nt*8 + 2*t;
            float c0 = cv[e0], c1 = cv[e0+1];
            float* ep0 = eaOut + (size_t)(eblk+e0)*384;
            float* ep1 = eaOut + (size_t)(eblk+e0+1)*384;
            ep0[oA] = siluf(d[0][nt][0]+bA)*c0;
            ep1[oA] = siluf(d[0][nt][1]+bA)*c1;
            ep0[oB] = siluf(d[0][nt][2]+bB)*c0;
            ep1[oB] = siluf(d[0][nt][3]+bB)*c1;
        }
    }
}

// ---------------- gather segment-sum + O(3) node update ----------------
__global__ void __launch_bounds__(128) k_gather_update(const int* __restrict__ ei,
                                                       const float* __restrict__ q,
                                                       const float* __restrict__ ea){
    int n = blockIdx.x;
    int h = threadIdx.x;
    int s = g_row[n], e1 = g_row[n+1];
    float cm[9];
    #pragma unroll
    for(int d=0;d<9;d++) cm[d]=0.f;
    for(int t=s;t<e1;t++){
        int e = g_eord[t];
        int dst = ei[NE + e];
        const float* ep = ea + (size_t)e*384;
        float a0=ep[h], a1=ep[128+h], a2=ep[256+h];
        int di = dst*HH + h;
        cm[0] += a0*g_cM[0*NH+di];
        cm[1] += a1*g_cM[1*NH+di];
        cm[2] += a1*g_cM[2*NH+di];
        cm[3] += a1*g_cM[3*NH+di];
        cm[4] += a2*g_cM[4*NH+di];
        cm[5] += a2*g_cM[5*NH+di];
        cm[6] += a2*g_cM[6*NH+di];
        cm[7] += a2*g_cM[7*NH+di];
        cm[8] += a2*g_cM[8*NH+di];
    }
    int idx = n*HH + h;
    float cy[9];
    #pragma unroll
    for(int d=0;d<9;d++) cy[d]=g_cM[d*NH+idx];
    float M[9], Y[9];
    rec(cm,M); rec(cy,Y);
    float AB[9];
    #pragma unroll
    for(int r=0;r<9;r++) AB[r]=0.f;
    mmadd(M,Y,AB); mmadd(Y,M,AB);
    float f = 1.f + 0.1f*q[n];
    float T[9]; float nrm=0.f;
    #pragma unroll
    for(int r=0;r<9;r++){ T[r]=f*AB[r]; nrm += T[r]*T[r]; }
    float inv = 1.f/(nrm+1.f);
    float c2[9]; tocompact(T,inv,c2);
    #pragma unroll
    for(int d=0;d<9;d++) g_c2[d*NH+idx]=c2[d];
}

// ---------------- final node update ----------------
__global__ void k_upd_b(const float* __restrict__ q, float* __restrict__ Xout){
    int idx = blockIdx.x*blockDim.x + threadIdx.x;
    if(idx>=NH) return;
    float c[9];
    #pragma unroll
    for(int d=0;d<9;d++) c[d]=g_dXc[d*NH+idx];
    float dx[9]; rec(c,dx);
    float f = 1.f + 0.1f*q[idx>>7];
    float D2[9];
    #pragma unroll
    for(int r=0;r<9;r++) D2[r]=0.f;
    mmadd(dx,dx,D2);
    #pragma unroll
    for(int r=0;r<9;r++)
        Xout[(size_t)idx*9+r] = g_Xn[(size_t)idx*9+r] + dx[r] + f*D2[r];
}

// ---------------- launcher: two-stream DAG (fork/join via events) --------------
extern "C" void kernel_launch(void* const* d_in, const int* in_sizes, int n_in,
                              void* d_out, int out_size){
    const float* X    = (const float*)d_in[0];
    const float* attr = (const float*)d_in[1];
    const float* ewt  = (const float*)d_in[2];
    const float* q    = (const float*)d_in[3];
    const float* Ws1  = (const float*)d_in[4];
    const float* bs1  = (const float*)d_in[5];
    const float* Ws2  = (const float*)d_in[6];
    const float* bs2  = (const float*)d_in[7];
    const float* Ws3  = (const float*)d_in[8];
    const float* bs3  = (const float*)d_in[9];
    const float* Wt   = (const float*)d_in[10];
    const int*   ei   = (const int*)d_in[11];
    float* out = (float*)d_out;

    // one-time init (first call is the uncaptured correctness run)
    static cudaStream_t s2 = nullptr;
    static cudaEvent_t evF = nullptr, evR = nullptr, evM = nullptr;
    if(!s2){
        cudaStreamCreateWithFlags(&s2, cudaStreamNonBlocking);
        cudaEventCreateWithFlags(&evF, cudaEventDisableTiming);
        cudaEventCreateWithFlags(&evR, cudaEventDisableTiming);
        cudaEventCreateWithFlags(&evM, cudaEventDisableTiming);
        cudaFuncSetAttribute(k_mlp_mma, cudaFuncAttributeMaxDynamicSharedMemorySize,
                             MLP_SMEMW*4);
        cudaFuncSetAttribute(k_mix_mma, cudaFuncAttributeMaxDynamicSharedMemorySize,
                             MIX_SMEMW*4);
    }

    float* ea0; cudaGetSymbolAddress((void**)&ea0, g_ea0);
    float* ea1; cudaGetSymbolAddress((void**)&ea1, g_ea1);

    // main: prep, then MLP0
    k_prep_w<<<264,256>>>(Ws1,Ws2,Ws3,Wt);
    cudaEventRecord(evF, 0);
    cudaStreamWaitEvent(s2, evF, 0);

    // s2 branch: CSR build + layer-0 node planes, then MLP1 (independent of layer 0)
    k_count<<<NE/256,256,0,s2>>>(ei);
    k_node_prep<<<NH/256,256,0,s2>>>(X);
    k_mix_mma<<<dim3(16,9),512,MIX_SMEMW*4,s2>>>(0, 0);
    k_scan<<<1,1024,0,s2>>>();
    k_place<<<NE/256,256,0,s2>>>(ei);
    cudaEventRecord(evR, s2);
    k_mlp_mma<<<NE/128,512,MLP_SMEMW*4,s2>>>(attr, ewt, bs1+128, bs2+256, bs3+384, 1, ea1);
    cudaEventRecord(evM, s2);

    // main branch: MLP0 runs concurrently with s2
    k_mlp_mma<<<NE/128,512,MLP_SMEMW*4>>>(attr, ewt, bs1, bs2, bs3, 0, ea0);

    // layer 0 tail (needs CSR + mix0_0 from s2)
    cudaStreamWaitEvent(0, evR, 0);
    k_gather_update<<<NA,128>>>(ei, q, ea0);
    k_mix_mma<<<dim3(16,9),512,MIX_SMEMW*4>>>(1, 3);
    k_upd_b<<<NH/256,256>>>(q, out);

    // layer 1 (MLP1 already computed on s2)
    k_node_prep<<<NH/256,256>>>(out);
    k_mix_mma<<<dim3(16,9),512,MIX_SMEMW*4>>>(0, 6);
    cudaStreamWaitEvent(0, evM, 0);
    k_gather_update<<<NA,128>>>(ei, q, ea1);
    k_mix_mma<<<dim3(16,9),512,MIX_SMEMW*4>>>(1, 9);
    k_upd_b<<<NH/256,256>>>(q, out);
}

// round 15
// speedup vs baseline: 1.0417x; 1.0417x over previous
#include <cuda_runtime.h>
#include <cstdint>
#include <cstddef>

#define NA 2048
#define HH 128
#define NE 32768
#define RR 32
#define NH (NA*HH)
#define CUT 4.5f

// ---------------- scratch (static device globals; no allocations) ----------------
__device__ float g_ea[NE*384];          // edge MLP output, [e][3][128]
__device__ float g_Xn[NH*9];
__device__ float g_cA[9*NH];
__device__ float g_cM[9*NH];
__device__ float g_c2[9*NH];
__device__ float g_dXc[9*NH];
__device__ unsigned g_W1f[2*8*2*32*8];      // bf16 hi/lo fragment images
__device__ unsigned g_W2f[2*16*8*32*8];
__device__ unsigned g_W3f[2*24*16*32*8];    // W3 output-permuted: o' = c*128+h
__device__ unsigned g_WmF[12*8*8*32*8];     // Wt fragment images for k_mix_mma
__device__ int   g_cnt[NA];
__device__ int   g_cur[NA];
__device__ int   g_row[NA+1];
__device__ int   g_eord[NE];

typedef unsigned long long u64;
typedef unsigned u32;

// ---------------- generic helpers ----------------
__device__ __forceinline__ float siluf(float x){ return x / (1.f + __expf(-x)); }

__device__ __forceinline__ void split_pair(float x, float y, u32& hi, u32& lo){
    u32 ux=__float_as_uint(x), uy=__float_as_uint(y);
    float rx = x - __uint_as_float(ux&0xFFFF0000u);
    float ry = y - __uint_as_float(uy&0xFFFF0000u);
    hi = (ux>>16) | (uy & 0xFFFF0000u);
    lo = (__float_as_uint(rx)>>16) | (__float_as_uint(ry)&0xFFFF0000u);
}

__device__ __forceinline__ int wpos(int w){ return 2*(w&3) + (w>>2); }

__device__ __forceinline__ void st_hl(u32* hiP, u32* loP, int padw, int e, int o, float v){
    u32 u = __float_as_uint(v);
    float r = v - __uint_as_float(u&0xFFFF0000u);
    int w = (o&15)>>1;
    int idx = e*padw + (o>>4)*8 + wpos(w);
    unsigned short* hp = (unsigned short*)(hiP+idx) + (o&1);
    unsigned short* lp = (unsigned short*)(loP+idx) + (o&1);
    *hp = (unsigned short)(u>>16);
    *lp = (unsigned short)(__float_as_uint(r)>>16);
}

__device__ __forceinline__ void mma16(float* d, const u32* a, const u32* b){
    asm volatile("mma.sync.aligned.m16n8k16.row.col.f32.bf16.bf16.f32 "
        "{%0,%1,%2,%3}, {%4,%5,%6,%7}, {%8,%9}, {%0,%1,%2,%3};"
        : "+f"(d[0]),"+f"(d[1]),"+f"(d[2]),"+f"(d[3])
        : "r"(a[0]),"r"(a[1]),"r"(a[2]),"r"(a[3]), "r"(b[0]),"r"(b[1]));
}

struct WF { uint4 h, l; };
__device__ __forceinline__ void ldwf(const uint4* __restrict__ W, int idx, WF& w){
    w.h = W[idx*2]; w.l = W[idx*2+1];
}

template<int M>
__device__ __forceinline__ void do_mma16_M(float (&d)[M][8][4], const WF (&w)[M],
                                           const u32* __restrict__ hiP,
                                           const u32* __restrict__ loP,
                                           int padw, int ebase, int kc8, int g, int t){
    #pragma unroll
    for(int nt=0;nt<8;nt++){
        int e = ebase + nt*8 + g;
        uint2 bh = *(const uint2*)&hiP[e*padw + kc8 + 2*t];
        uint2 bl = *(const uint2*)&loP[e*padw + kc8 + 2*t];
        #pragma unroll
        for(int m=0;m<M;m++){
            const u32* ah = (const u32*)&w[m].h;
            const u32* al = (const u32*)&w[m].l;
            mma16(d[m][nt],ah,(const u32*)&bh);
            mma16(d[m][nt],ah,(const u32*)&bl);
            mma16(d[m][nt],al,(const u32*)&bh);
        }
    }
}

// compact basis: {i0, a01, a02, a12, s00, s01, s02, s11, s12}
__device__ __forceinline__ void tocompact(const float* t, float s, float* c){
    float i0 = (t[0]+t[4]+t[8])*(1.f/3.f);
    c[0] = i0*s;
    c[1] = 0.5f*(t[1]-t[3])*s;
    c[2] = 0.5f*(t[2]-t[6])*s;
    c[3] = 0.5f*(t[5]-t[7])*s;
    c[4] = (t[0]-i0)*s;
    c[5] = 0.5f*(t[1]+t[3])*s;
    c[6] = 0.5f*(t[2]+t[6])*s;
    c[7] = (t[4]-i0)*s;
    c[8] = 0.5f*(t[5]+t[7])*s;
}
__device__ __forceinline__ void rec(const float* c, float* t){
    float i0=c[0], a01=c[1], a02=c[2], a12=c[3];
    float s00=c[4], s01=c[5], s02=c[6], s11=c[7], s12=c[8];
    t[0]=i0+s00;  t[1]=a01+s01; t[2]=a02+s02;
    t[3]=s01-a01; t[4]=i0+s11;  t[5]=a12+s12;
    t[6]=s02-a02; t[7]=s12-a12; t[8]=i0-s00-s11;
}
__device__ __forceinline__ void mmadd(const float* A, const float* B, float* C){
    #pragma unroll
    for(int i=0;i<3;i++){
        #pragma unroll
        for(int j=0;j<3;j++)
            C[i*3+j] += A[i*3+0]*B[0*3+j] + A[i*3+1]*B[1*3+j] + A[i*3+2]*B[2*3+j];
    }
}

// ---------------- weight prep: bf16 hi/lo fragment images (+cnt zero) ----------
__device__ __forceinline__ void packw(const float* __restrict__ W, int stride,
                                      int r, int k, u32& hi, u32& lo){
    float w0=W[r*stride+k], w1=W[r*stride+k+1];
    u32 u0=__float_as_uint(w0);
    float r0=w0-__uint_as_float(u0&0xFFFF0000u);
    float r1=w1-__uint_as_float(__float_as_uint(w1)&0xFFFF0000u);
    hi = (u0>>16) | (__float_as_uint(w1)&0xFFFF0000u);
    lo = (__float_as_uint(r0)>>16) | (__float_as_uint(r1)&0xFFFF0000u);
}

__global__ void k_prep_w(const float* __restrict__ Ws1, const float* __restrict__ Ws2,
                         const float* __restrict__ Ws3, const float* __restrict__ Wt){
    int stride = gridDim.x*blockDim.x;
    int t0 = blockIdx.x*blockDim.x + threadIdx.x;
    if(t0 < NA){ g_cnt[t0]=0; g_cur[t0]=0; }
    for(int i=t0;i<2*8*2*32;i+=stride){
        int l=i>>9, r=i&511, ot=r>>6, r2=r&63, kc=r2>>5, lane=r2&31;
        int g=lane>>2, t=lane&3, o0=ot*16, kb=kc*16;
        const float* W = Ws1 + (size_t)l*128*32;
        u32 f[8];
        packw(W,32,o0+g,  kb+2*t,  f[0],f[4]);
        packw(W,32,o0+g+8,kb+2*t,  f[1],f[5]);
        packw(W,32,o0+g,  kb+2*t+8,f[2],f[6]);
        packw(W,32,o0+g+8,kb+2*t+8,f[3],f[7]);
        u32* dst = g_W1f + ((size_t)l*512 + (ot*2+kc)*32 + lane)*8;
        #pragma unroll
        for(int j=0;j<8;j++) dst[j]=f[j];
    }
    for(int i=t0;i<2*16*8*32;i+=stride){
        int l=i>>12, r=i&4095, ot=r>>8, r2=r&255, kc=r2>>5, lane=r2&31;
        int g=lane>>2, t=lane&3, o0=ot*16, kb=kc*16;
        const float* W = Ws2 + (size_t)l*256*128;
        u32 f[8];
        packw(W,128,o0+g,  kb+2*t,  f[0],f[4]);
        packw(W,128,o0+g+8,kb+2*t,  f[1],f[5]);
        packw(W,128,o0+g,  kb+2*t+8,f[2],f[6]);
        packw(W,128,o0+g+8,kb+2*t+8,f[3],f[7]);
        u32* dst = g_W2f + ((size_t)l*4096 + (ot*8+kc)*32 + lane)*8;
        #pragma unroll
        for(int j=0;j<8;j++) dst[j]=f[j];
    }
    for(int i=t0;i<2*24*16*32;i+=stride){
        int l=i/12288, r=i%12288, ot=r>>9, r2=r&511, kc=r2>>5, lane=r2&31;
        int g=lane>>2, t=lane&3, o0=ot*16, kb=kc*16;
        const float* W = Ws3 + (size_t)l*384*256;
        int rows[2] = { o0+g, o0+g+8 };
        u32 f[8];
        #pragma unroll
        for(int rr=0;rr<2;rr++){
            int op = rows[rr];
            int j = (op&127)*3 + (op>>7);
            packw(W,256,j,kb+2*t,  f[rr],  f[rr+4]);
            packw(W,256,j,kb+2*t+8,f[rr+2],f[rr+6]);
        }
        u32* dst = g_W3f + ((size_t)l*12288 + (ot*16+kc)*32 + lane)*8;
        #pragma unroll
        for(int j=0;j<8;j++) dst[j]=f[j];
    }
    for(int i=t0;i<12*8*8*32;i+=stride){
        int lm=i/2048, r=i%2048, ot=r>>8, r2=r&255, kc=r2>>5, lane=r2&31;
        int g=lane>>2, t=lane&3, o0=ot*16, kb=kc*16;
        const float* W = Wt + (size_t)lm*16384;
        u32 f[8];
        packw(W,128,o0+g,  kb+2*t,  f[0],f[4]);
        packw(W,128,o0+g+8,kb+2*t,  f[1],f[5]);
        packw(W,128,o0+g,  kb+2*t+8,f[2],f[6]);
        packw(W,128,o0+g+8,kb+2*t+8,f[3],f[7]);
        u32* dst = g_WmF + ((size_t)(lm*64 + ot*8+kc)*32 + lane)*8;
        #pragma unroll
        for(int j=0;j<8;j++) dst[j]=f[j];
    }
}

// ---------------- CSR build ----------------
__global__ void k_count(const int* __restrict__ ei){
    int e = blockIdx.x*blockDim.x + threadIdx.x;
    if(e<NE) atomicAdd(&g_cnt[ei[e]], 1);
}
__global__ void k_scan(){
    __shared__ int sh[1024];
    int t = threadIdx.x;
    int v0 = g_cnt[2*t], v1 = g_cnt[2*t+1];
    int s = v0+v1;
    sh[t]=s; __syncthreads();
    #pragma unroll
    for(int off=1; off<1024; off<<=1){
        int x = (t>=off)? sh[t-off] : 0;
        __syncthreads();
        sh[t] += x;
        __syncthreads();
    }
    int incl = sh[t];
    int excl = incl - s;
    g_row[2*t]   = excl;
    g_row[2*t+1] = excl + v0;
    if(t==1023) g_row[2048]=incl;
}
__global__ void k_place(const int* __restrict__ ei){
    int e = blockIdx.x*blockDim.x + threadIdx.x;
    if(e<NE){
        int s = ei[e];
        int p = atomicAdd(&g_cur[s],1);
        g_eord[g_row[s]+p] = e;
    }
}

// ---------------- node prep ----------------
__global__ void k_node_prep(const float* __restrict__ Xin){
    int idx = blockIdx.x*blockDim.x + threadIdx.x;
    if(idx>=NH) return;
    float t[9]; float nrm=0.f;
    #pragma unroll
    for(int r=0;r<9;r++){ t[r]=Xin[(size_t)idx*9+r]; nrm += t[r]*t[r]; }
    float inv = 1.f/(nrm+1.f);
    #pragma unroll
    for(int r=0;r<9;r++){ t[r]*=inv; g_Xn[(size_t)idx*9+r]=t[r]; }
    float c[9]; tocompact(t,1.f,c);
    #pragma unroll
    for(int d=0;d<9;d++) g_cA[d*NH+idx]=c[d];
}

// ---------------- channel mix on tensor cores: 64-node blocks, 4 blocks/SM ----
// grid (32, 9): 64 nodes x plane d. 256 threads = 8 warps = 8 out-slices.
#define MIX_PADW 72
#define MIX_SMEMW (2*64*MIX_PADW)

__global__ void __launch_bounds__(256,4)
k_mix_mma(int which, int wbase){
    extern __shared__ u32 smu[];
    u32* inh = smu;
    u32* inl = smu + 64*MIX_PADW;
    const float* in  = which ? g_c2  : g_cA;
    float*       out = which ? g_dXc : g_cM;
    int d = blockIdx.y;
    int m = (d==0)?0:((d<4)?1:2);
    int lm = wbase + m;
    int nblk = blockIdx.x*64;
    int tid = threadIdx.x;
    int warp = tid>>5, lane = tid&31;
    int g = lane>>2, t = lane&3;
    int hw = warp;                      // out-slice 0..7

    const float* src = in + (size_t)d*NH + (size_t)nblk*HH;
    // stage 64x128 fp32 into hi/lo bf16 planes (permuted word order)
    for(int i=tid;i<2048;i+=256){
        int e=i>>5, k4=(i&31)<<2;
        float4 v = *(const float4*)&src[e*128 + k4];
        int kc = k4>>4;
        int lw = (k4&15)>>1;
        u32 hi0,lo0,hi1,lo1;
        split_pair(v.x,v.y,hi0,lo0);
        split_pair(v.z,v.w,hi1,lo1);
        int base = e*MIX_PADW + kc*8;
        inh[base + wpos(lw)]   = hi0;
        inh[base + wpos(lw+1)] = hi1;
        inl[base + wpos(lw)]   = lo0;
        inl[base + wpos(lw+1)] = lo1;
    }
    __syncthreads();

    const uint4* Wm = (const uint4*)(g_WmF + (size_t)lm*64*32*8);
    float dacc[1][8][4];
    #pragma unroll
    for(int nt=0;nt<8;nt++){ dacc[0][nt][0]=dacc[0][nt][1]=dacc[0][nt][2]=dacc[0][nt][3]=0.f; }
    WF wa[1], wb[1];
    ldwf(Wm, (hw*8+0)*32+lane, wa[0]);
    #pragma unroll 1
    for(int kc=0;kc<8;kc+=2){
        ldwf(Wm, (hw*8+kc+1)*32+lane, wb[0]);
        do_mma16_M<1>(dacc, wa, inh, inl, MIX_PADW, 0, kc*8, g, t);
        if(kc+2<8) ldwf(Wm, (hw*8+kc+2)*32+lane, wa[0]);
        do_mma16_M<1>(dacc, wb, inh, inl, MIX_PADW, 0, (kc+1)*8, g, t);
    }
    float* outp = out + (size_t)d*NH + (size_t)nblk*HH;
    int oA = hw*16 + g, oB = oA + 8;
    #pragma unroll
    for(int nt=0;nt<8;nt++){
        int e0 = nt*8 + 2*t;
        outp[e0*128 + oA]     = dacc[0][nt][0];
        outp[(e0+1)*128 + oA] = dacc[0][nt][1];
        outp[e0*128 + oB]     = dacc[0][nt][2];
        outp[(e0+1)*128 + oB] = dacc[0][nt][3];
    }
}

// ---------------- edge MLP: bf16 split mma, hi/lo planes, m-tile B-reuse ------
#define A_PADW  40
#define H1_PADW 72
#define H2_PADW 136
#define MLP_SMEMW (128 + 2*128*H1_PADW + 2*128*H2_PADW)

__global__ void __launch_bounds__(512,1)
k_mlp_mma(const float* __restrict__ attr, const float* __restrict__ ewt,
          const float* __restrict__ b1, const float* __restrict__ b2,
          const float* __restrict__ b3raw, int l){
    extern __shared__ u32 smu[];
    float* cv = (float*)smu;
    u32* h1h = smu + 128;
    u32* h1l = h1h + 128*H1_PADW;
    u32* h2h = h1l + 128*H1_PADW;
    u32* h2l = h2h + 128*H2_PADW;
    u32* aah = h2h;
    u32* aal = h2l;
    int tid = threadIdx.x;
    int warp = tid>>5, lane = tid&31;
    int g = lane>>2, t = lane&3;
    int hw = warp>>1;
    int ebase = (warp&1)*64;
    int eblk = blockIdx.x*128;

    const uint4* W1 = (const uint4*)(g_W1f + (size_t)l*4096);
    const uint4* W2 = (const uint4*)(g_W2f + (size_t)l*32768);
    const uint4* W3 = (const uint4*)(g_W3f + (size_t)l*98304);

    for(int i=tid;i<1024;i+=512){
        int e=i>>3, k4=(i&7)<<2;
        float4 v = *(const float4*)&attr[(size_t)(eblk+e)*32 + k4];
        int kc = k4>>4;
        int lw = (k4&15)>>1;
        u32 hi0,lo0,hi1,lo1;
        split_pair(v.x,v.y,hi0,lo0);
        split_pair(v.z,v.w,hi1,lo1);
        int base = e*A_PADW + kc*8;
        aah[base + wpos(lw)]   = hi0;
        aah[base + wpos(lw+1)] = hi1;
        aal[base + wpos(lw)]   = lo0;
        aal[base + wpos(lw+1)] = lo1;
    }
    if(tid<128){
        float wv = ewt[eblk+tid];
        cv[tid] = (wv < CUT) ? 0.5f*(cosf(wv*(3.14159265358979f/CUT))+1.f) : 0.f;
    }
    __syncthreads();

    // ---- stage 1 ----
    {
        float d[1][8][4];
        #pragma unroll
        for(int nt=0;nt<8;nt++){ d[0][nt][0]=d[0][nt][1]=d[0][nt][2]=d[0][nt][3]=0.f; }
        WF wa[1], wb[1];
        ldwf(W1, (hw*2+0)*32+lane, wa[0]);
        ldwf(W1, (hw*2+1)*32+lane, wb[0]);
        do_mma16_M<1>(d, wa, aah, aal, A_PADW, ebase, 0, g, t);
        do_mma16_M<1>(d, wb, aah, aal, A_PADW, ebase, 8, g, t);
        int o = hw*16;
        float bA=b1[o+g], bB=b1[o+g+8];
        #pragma unroll
        for(int nt=0;nt<8;nt++){
            int e = ebase + nt*8 + 2*t;
            st_hl(h1h,h1l,H1_PADW,e,  o+g,  siluf(d[0][nt][0]+bA));
            st_hl(h1h,h1l,H1_PADW,e+1,o+g,  siluf(d[0][nt][1]+bA));
            st_hl(h1h,h1l,H1_PADW,e,  o+g+8,siluf(d[0][nt][2]+bB));
            st_hl(h1h,h1l,H1_PADW,e+1,o+g+8,siluf(d[0][nt][3]+bB));
        }
    }
    __syncthreads();

    // ---- stage 2: single pass, 2 m-tiles ----
    {
        float d[2][8][4];
        #pragma unroll
        for(int m=0;m<2;m++)
            #pragma unroll
            for(int nt=0;nt<8;nt++){ d[m][nt][0]=d[m][nt][1]=d[m][nt][2]=d[m][nt][3]=0.f; }
        WF wa[2], wb[2];
        #pragma unroll
        for(int m=0;m<2;m++) ldwf(W2, ((hw*2+m)*8+0)*32+lane, wa[m]);
        #pragma unroll 1
        for(int kc=0;kc<8;kc+=2){
            #pragma unroll
            for(int m=0;m<2;m++) ldwf(W2, ((hw*2+m)*8+kc+1)*32+lane, wb[m]);
            do_mma16_M<2>(d, wa, h1h, h1l, H1_PADW, ebase, kc*8, g, t);
            if(kc+2<8){
                #pragma unroll
                for(int m=0;m<2;m++) ldwf(W2, ((hw*2+m)*8+kc+2)*32+lane, wa[m]);
            }
            do_mma16_M<2>(d, wb, h1h, h1l, H1_PADW, ebase, (kc+1)*8, g, t);
        }
        #pragma unroll
        for(int m=0;m<2;m++){
            int oo = hw*32 + m*16;
            float bA=b2[oo+g], bB=b2[oo+g+8];
            #pragma unroll
            for(int nt=0;nt<8;nt++){
                int e = ebase + nt*8 + 2*t;
                st_hl(h2h,h2l,H2_PADW,e,  oo+g,  siluf(d[m][nt][0]+bA));
                st_hl(h2h,h2l,H2_PADW,e+1,oo+g,  siluf(d[m][nt][1]+bA));
                st_hl(h2h,h2l,H2_PADW,e,  oo+g+8,siluf(d[m][nt][2]+bB));
                st_hl(h2h,h2l,H2_PADW,e+1,oo+g+8,siluf(d[m][nt][3]+bB));
            }
        }
    }
    __syncthreads();

    // ---- stage 3: pass A = 2 m-tiles, pass B = 1 m-tile ----
    {
        float d[2][8][4];
        #pragma unroll
        for(int m=0;m<2;m++)
            #pragma unroll
            for(int nt=0;nt<8;nt++){ d[m][nt][0]=d[m][nt][1]=d[m][nt][2]=d[m][nt][3]=0.f; }
        WF wa[2], wb[2];
        #pragma unroll
        for(int m=0;m<2;m++) ldwf(W3, ((hw*3+m)*16+0)*32+lane, wa[m]);
        #pragma unroll 1
        for(int kc=0;kc<16;kc+=2){
            #pragma unroll
            for(int m=0;m<2;m++) ldwf(W3, ((hw*3+m)*16+kc+1)*32+lane, wb[m]);
            do_mma16_M<2>(d, wa, h2h, h2l, H2_PADW, ebase, kc*8, g, t);
            if(kc+2<16){
                #pragma unroll
                for(int m=0;m<2;m++) ldwf(W3, ((hw*3+m)*16+kc+2)*32+lane, wa[m]);
            }
            do_mma16_M<2>(d, wb, h2h, h2l, H2_PADW, ebase, (kc+1)*8, g, t);
        }
        #pragma unroll
        for(int m=0;m<2;m++){
            int oA = hw*48 + m*16 + g, oB = oA + 8;
            float bA = b3raw[(oA&127)*3 + (oA>>7)];
            float bB = b3raw[(oB&127)*3 + (oB>>7)];
            #pragma unroll
            for(int nt=0;nt<8;nt++){
                int e0 = ebase + nt*8 + 2*t;
                float c0 = cv[e0], c1 = cv[e0+1];
                float* ep0 = g_ea + (size_t)(eblk+e0)*384;
                float* ep1 = g_ea + (size_t)(eblk+e0+1)*384;
                ep0[oA] = siluf(d[m][nt][0]+bA)*c0;
                ep1[oA] = siluf(d[m][nt][1]+bA)*c1;
                ep0[oB] = siluf(d[m][nt][2]+bB)*c0;
                ep1[oB] = siluf(d[m][nt][3]+bB)*c1;
            }
        }
    }
    {
        float d[1][8][4];
        #pragma unroll
        for(int nt=0;nt<8;nt++){ d[0][nt][0]=d[0][nt][1]=d[0][nt][2]=d[0][nt][3]=0.f; }
        WF wa[1], wb[1];
        ldwf(W3, ((hw*3+2)*16+0)*32+lane, wa[0]);
        #pragma unroll 1
        for(int kc=0;kc<16;kc+=2){
            ldwf(W3, ((hw*3+2)*16+kc+1)*32+lane, wb[0]);
            do_mma16_M<1>(d, wa, h2h, h2l, H2_PADW, ebase, kc*8, g, t);
            if(kc+2<16) ldwf(W3, ((hw*3+2)*16+kc+2)*32+lane, wa[0]);
            do_mma16_M<1>(d, wb, h2h, h2l, H2_PADW, ebase, (kc+1)*8, g, t);
        }
        int oA = hw*48 + 2*16 + g, oB = oA + 8;
        float bA = b3raw[(oA&127)*3 + (oA>>7)];
        float bB = b3raw[(oB&127)*3 + (oB>>7)];
        #pragma unroll
        for(int nt=0;nt<8;nt++){
            int e0 = ebase + nt*8 + 2*t;
            float c0 = cv[e0], c1 = cv[e0+1];
            float* ep0 = g_ea + (size_t)(eblk+e0)*384;
            float* ep1 = g_ea + (size_t)(eblk+e0+1)*384;
            ep0[oA] = siluf(d[0][nt][0]+bA)*c0;
            ep1[oA] = siluf(d[0][nt][1]+bA)*c1;
            ep0[oB] = siluf(d[0][nt][2]+bB)*c0;
            ep1[oB] = siluf(d[0][nt][3]+bB)*c1;
        }
    }
}

// ---------------- gather segment-sum + O(3) node update ----------------
__global__ void __launch_bounds__(128) k_gather_update(const int* __restrict__ ei,
                                                       const float* __restrict__ q){
    int n = blockIdx.x;
    int h = threadIdx.x;
    int s = g_row[n], e1 = g_row[n+1];
    float cm[9];
    #pragma unroll
    for(int d=0;d<9;d++) cm[d]=0.f;
    for(int t=s;t<e1;t++){
        int e = g_eord[t];
        int dst = ei[NE + e];
        const float* ep = g_ea + (size_t)e*384;
        float a0=ep[h], a1=ep[128+h], a2=ep[256+h];
        int di = dst*HH + h;
        cm[0] += a0*g_cM[0*NH+di];
        cm[1] += a1*g_cM[1*NH+di];
        cm[2] += a1*g_cM[2*NH+di];
        cm[3] += a1*g_cM[3*NH+di];
        cm[4] += a2*g_cM[4*NH+di];
        cm[5] += a2*g_cM[5*NH+di];
        cm[6] += a2*g_cM[6*NH+di];
        cm[7] += a2*g_cM[7*NH+di];
        cm[8] += a2*g_cM[8*NH+di];
    }
    int idx = n*HH + h;
    float cy[9];
    #pragma unroll
    for(int d=0;d<9;d++) cy[d]=g_cM[d*NH+idx];
    float M[9], Y[9];
    rec(cm,M); rec(cy,Y);
    float AB[9];
    #pragma unroll
    for(int r=0;r<9;r++) AB[r]=0.f;
    mmadd(M,Y,AB); mmadd(Y,M,AB);
    float f = 1.f + 0.1f*q[n];
    float T[9]; float nrm=0.f;
    #pragma unroll
    for(int r=0;r<9;r++){ T[r]=f*AB[r]; nrm += T[r]*T[r]; }
    float inv = 1.f/(nrm+1.f);
    float c2[9]; tocompact(T,inv,c2);
    #pragma unroll
    for(int d=0;d<9;d++) g_c2[d*NH+idx]=c2[d];
}

// ---------------- final node update ----------------
__global__ void k_upd_b(const float* __restrict__ q, float* __restrict__ Xout){
    int idx = blockIdx.x*blockDim.x + threadIdx.x;
    if(idx>=NH) return;
    float c[9];
    #pragma unroll
    for(int d=0;d<9;d++) c[d]=g_dXc[d*NH+idx];
    float dx[9]; rec(c,dx);
    float f = 1.f + 0.1f*q[idx>>7];
    float D2[9];
    #pragma unroll
    for(int r=0;r<9;r++) D2[r]=0.f;
    mmadd(dx,dx,D2);
    #pragma unroll
    for(int r=0;r<9;r++)
        Xout[(size_t)idx*9+r] = g_Xn[(size_t)idx*9+r] + dx[r] + f*D2[r];
}

// ---------------- launcher (R13 schedule; k_mix_mma at index 3 for ncu) --------
extern "C" void kernel_launch(void* const* d_in, const int* in_sizes, int n_in,
                              void* d_out, int out_size){
    const float* X    = (const float*)d_in[0];
    const float* attr = (const float*)d_in[1];
    const float* ewt  = (const float*)d_in[2];
    const float* q    = (const float*)d_in[3];
    const float* Ws1  = (const float*)d_in[4];
    const float* bs1  = (const float*)d_in[5];
    const float* Ws2  = (const float*)d_in[6];
    const float* bs2  = (const float*)d_in[7];
    const float* Ws3  = (const float*)d_in[8];
    const float* bs3  = (const float*)d_in[9];
    const float* Wt   = (const float*)d_in[10];
    const int*   ei   = (const int*)d_in[11];
    float* out = (float*)d_out;

    cudaFuncSetAttribute(k_mlp_mma, cudaFuncAttributeMaxDynamicSharedMemorySize,
                         MLP_SMEMW*4);
    cudaFuncSetAttribute(k_mix_mma, cudaFuncAttributeMaxDynamicSharedMemorySize,
                         MIX_SMEMW*4);

    k_prep_w<<<264,256>>>(Ws1,Ws2,Ws3,Wt);                                   // 0 (+zero cnt)
    k_node_prep<<<NH/256,256>>>(X);                                          // 1
    k_count<<<NE/256,256>>>(ei);                                             // 2
    k_mix_mma<<<dim3(32,9),256,MIX_SMEMW*4>>>(0, 0);                         // 3 <- ncu
    k_mlp_mma<<<NE/128,512,MLP_SMEMW*4>>>(attr, ewt, bs1, bs2, bs3, 0);      // 4
    k_scan<<<1,1024>>>();                                                    // 5
    k_place<<<NE/256,256>>>(ei);                                             // 6
    k_gather_update<<<NA,128>>>(ei, q);                                      // 7
    k_mix_mma<<<dim3(32,9),256,MIX_SMEMW*4>>>(1, 3);                         // 8
    k_upd_b<<<NH/256,256>>>(q, out);                                         // 9

    // layer 1 (CSR already built)
    k_node_prep<<<NH/256,256>>>(out);
    k_mix_mma<<<dim3(32,9),256,MIX_SMEMW*4>>>(0, 6);
    k_mlp_mma<<<NE/128,512,MLP_SMEMW*4>>>(attr, ewt, bs1+128, bs2+256, bs3+384, 1);
    k_gather_update<<<NA,128>>>(ei, q);
    k_mix_mma<<<dim3(32,9),256,MIX_SMEMW*4>>>(1, 9);
    k_upd_b<<<NH/256,256>>>(q, out);
}

// round 16
// speedup vs baseline: 1.0540x; 1.0119x over previous
#include <cuda_runtime.h>
#include <cstdint>
#include <cstddef>

#define NA 2048
#define HH 128
#define NE 32768
#define RR 32
#define NH (NA*HH)
#define CUT 4.5f

// ---------------- scratch (static device globals; no allocations) ----------------
__device__ float g_ea[NE*384];          // edge MLP output, [e][3][128]
__device__ float g_Xn[NH*9];
__device__ float g_cA[9*NH];
__device__ float g_cM[9*NH];
__device__ float g_c2[9*NH];
__device__ float g_dXc[9*NH];
__device__ unsigned g_W1f[2*8*2*32*8];      // bf16 hi/lo fragment images
__device__ unsigned g_W2f[2*16*8*32*8];
__device__ unsigned g_W3f[2*24*16*32*8];    // W3 output-permuted: o' = c*128+h
__device__ unsigned g_WmF[12*8*8*32*8];     // Wt fragment images for k_mix_mma
__device__ int   g_cnt[NA];
__device__ int   g_cur[NA];
__device__ int   g_row[NA+1];
__device__ int   g_eord[NE];

typedef unsigned long long u64;
typedef unsigned u32;

// ---------------- generic helpers ----------------
__device__ __forceinline__ float siluf(float x){ return x / (1.f + __expf(-x)); }

__device__ __forceinline__ void split_pair(float x, float y, u32& hi, u32& lo){
    u32 ux=__float_as_uint(x), uy=__float_as_uint(y);
    float rx = x - __uint_as_float(ux&0xFFFF0000u);
    float ry = y - __uint_as_float(uy&0xFFFF0000u);
    hi = (ux>>16) | (uy & 0xFFFF0000u);
    lo = (__float_as_uint(rx)>>16) | (__float_as_uint(ry)&0xFFFF0000u);
}

__device__ __forceinline__ int wpos(int w){ return 2*(w&3) + (w>>2); }

__device__ __forceinline__ void st_hl(u32* hiP, u32* loP, int padw, int e, int o, float v){
    u32 u = __float_as_uint(v);
    float r = v - __uint_as_float(u&0xFFFF0000u);
    int w = (o&15)>>1;
    int idx = e*padw + (o>>4)*8 + wpos(w);
    unsigned short* hp = (unsigned short*)(hiP+idx) + (o&1);
    unsigned short* lp = (unsigned short*)(loP+idx) + (o&1);
    *hp = (unsigned short)(u>>16);
    *lp = (unsigned short)(__float_as_uint(r)>>16);
}

__device__ __forceinline__ void mma16(float* d, const u32* a, const u32* b){
    asm volatile("mma.sync.aligned.m16n8k16.row.col.f32.bf16.bf16.f32 "
        "{%0,%1,%2,%3}, {%4,%5,%6,%7}, {%8,%9}, {%0,%1,%2,%3};"
        : "+f"(d[0]),"+f"(d[1]),"+f"(d[2]),"+f"(d[3])
        : "r"(a[0]),"r"(a[1]),"r"(a[2]),"r"(a[3]), "r"(b[0]),"r"(b[1]));
}

struct WF { uint4 h, l; };
__device__ __forceinline__ void ldwf(const uint4* __restrict__ W, int idx, WF& w){
    w.h = W[idx*2]; w.l = W[idx*2+1];
}

template<int M>
__device__ __forceinline__ void do_mma16_M(float (&d)[M][8][4], const WF (&w)[M],
                                           const u32* __restrict__ hiP,
                                           const u32* __restrict__ loP,
                                           int padw, int ebase, int kc8, int g, int t){
    #pragma unroll
    for(int nt=0;nt<8;nt++){
        int e = ebase + nt*8 + g;
        uint2 bh = *(const uint2*)&hiP[e*padw + kc8 + 2*t];
        uint2 bl = *(const uint2*)&loP[e*padw + kc8 + 2*t];
        #pragma unroll
        for(int m=0;m<M;m++){
            const u32* ah = (const u32*)&w[m].h;
            const u32* al = (const u32*)&w[m].l;
            mma16(d[m][nt],ah,(const u32*)&bh);
            mma16(d[m][nt],ah,(const u32*)&bl);
            mma16(d[m][nt],al,(const u32*)&bh);
        }
    }
}

// compact basis: {i0, a01, a02, a12, s00, s01, s02, s11, s12}
__device__ __forceinline__ void tocompact(const float* t, float s, float* c){
    float i0 = (t[0]+t[4]+t[8])*(1.f/3.f);
    c[0] = i0*s;
    c[1] = 0.5f*(t[1]-t[3])*s;
    c[2] = 0.5f*(t[2]-t[6])*s;
    c[3] = 0.5f*(t[5]-t[7])*s;
    c[4] = (t[0]-i0)*s;
    c[5] = 0.5f*(t[1]+t[3])*s;
    c[6] = 0.5f*(t[2]+t[6])*s;
    c[7] = (t[4]-i0)*s;
    c[8] = 0.5f*(t[5]+t[7])*s;
}
__device__ __forceinline__ void rec(const float* c, float* t){
    float i0=c[0], a01=c[1], a02=c[2], a12=c[3];
    float s00=c[4], s01=c[5], s02=c[6], s11=c[7], s12=c[8];
    t[0]=i0+s00;  t[1]=a01+s01; t[2]=a02+s02;
    t[3]=s01-a01; t[4]=i0+s11;  t[5]=a12+s12;
    t[6]=s02-a02; t[7]=s12-a12; t[8]=i0-s00-s11;
}
__device__ __forceinline__ void mmadd(const float* A, const float* B, float* C){
    #pragma unroll
    for(int i=0;i<3;i++){
        #pragma unroll
        for(int j=0;j<3;j++)
            C[i*3+j] += A[i*3+0]*B[0*3+j] + A[i*3+1]*B[1*3+j] + A[i*3+2]*B[2*3+j];
    }
}

// ---------------- weight prep: bf16 hi/lo fragment images (+cnt zero) ----------
__device__ __forceinline__ void packw(const float* __restrict__ W, int stride,
                                      int r, int k, u32& hi, u32& lo){
    float w0=W[r*stride+k], w1=W[r*stride+k+1];
    u32 u0=__float_as_uint(w0);
    float r0=w0-__uint_as_float(u0&0xFFFF0000u);
    float r1=w1-__uint_as_float(__float_as_uint(w1)&0xFFFF0000u);
    hi = (u0>>16) | (__float_as_uint(w1)&0xFFFF0000u);
    lo = (__float_as_uint(r0)>>16) | (__float_as_uint(r1)&0xFFFF0000u);
}

__global__ void k_prep_w(const float* __restrict__ Ws1, const float* __restrict__ Ws2,
                         const float* __restrict__ Ws3, const float* __restrict__ Wt){
    int stride = gridDim.x*blockDim.x;
    int t0 = blockIdx.x*blockDim.x + threadIdx.x;
    if(t0 < NA){ g_cnt[t0]=0; g_cur[t0]=0; }
    for(int i=t0;i<2*8*2*32;i+=stride){
        int l=i>>9, r=i&511, ot=r>>6, r2=r&63, kc=r2>>5, lane=r2&31;
        int g=lane>>2, t=lane&3, o0=ot*16, kb=kc*16;
        const float* W = Ws1 + (size_t)l*128*32;
        u32 f[8];
        packw(W,32,o0+g,  kb+2*t,  f[0],f[4]);
        packw(W,32,o0+g+8,kb+2*t,  f[1],f[5]);
        packw(W,32,o0+g,  kb+2*t+8,f[2],f[6]);
        packw(W,32,o0+g+8,kb+2*t+8,f[3],f[7]);
        u32* dst = g_W1f + ((size_t)l*512 + (ot*2+kc)*32 + lane)*8;
        #pragma unroll
        for(int j=0;j<8;j++) dst[j]=f[j];
    }
    for(int i=t0;i<2*16*8*32;i+=stride){
        int l=i>>12, r=i&4095, ot=r>>8, r2=r&255, kc=r2>>5, lane=r2&31;
        int g=lane>>2, t=lane&3, o0=ot*16, kb=kc*16;
        const float* W = Ws2 + (size_t)l*256*128;
        u32 f[8];
        packw(W,128,o0+g,  kb+2*t,  f[0],f[4]);
        packw(W,128,o0+g+8,kb+2*t,  f[1],f[5]);
        packw(W,128,o0+g,  kb+2*t+8,f[2],f[6]);
        packw(W,128,o0+g+8,kb+2*t+8,f[3],f[7]);
        u32* dst = g_W2f + ((size_t)l*4096 + (ot*8+kc)*32 + lane)*8;
        #pragma unroll
        for(int j=0;j<8;j++) dst[j]=f[j];
    }
    for(int i=t0;i<2*24*16*32;i+=stride){
        int l=i/12288, r=i%12288, ot=r>>9, r2=r&511, kc=r2>>5, lane=r2&31;
        int g=lane>>2, t=lane&3, o0=ot*16, kb=kc*16;
        const float* W = Ws3 + (size_t)l*384*256;
        int rows[2] = { o0+g, o0+g+8 };
        u32 f[8];
        #pragma unroll
        for(int rr=0;rr<2;rr++){
            int op = rows[rr];
            int j = (op&127)*3 + (op>>7);
            packw(W,256,j,kb+2*t,  f[rr],  f[rr+4]);
            packw(W,256,j,kb+2*t+8,f[rr+2],f[rr+6]);
        }
        u32* dst = g_W3f + ((size_t)l*12288 + (ot*16+kc)*32 + lane)*8;
        #pragma unroll
        for(int j=0;j<8;j++) dst[j]=f[j];
    }
    for(int i=t0;i<12*8*8*32;i+=stride){
        int lm=i/2048, r=i%2048, ot=r>>8, r2=r&255, kc=r2>>5, lane=r2&31;
        int g=lane>>2, t=lane&3, o0=ot*16, kb=kc*16;
        const float* W = Wt + (size_t)lm*16384;
        u32 f[8];
        packw(W,128,o0+g,  kb+2*t,  f[0],f[4]);
        packw(W,128,o0+g+8,kb+2*t,  f[1],f[5]);
        packw(W,128,o0+g,  kb+2*t+8,f[2],f[6]);
        packw(W,128,o0+g+8,kb+2*t+8,f[3],f[7]);
        u32* dst = g_WmF + ((size_t)(lm*64 + ot*8+kc)*32 + lane)*8;
        #pragma unroll
        for(int j=0;j<8;j++) dst[j]=f[j];
    }
}

// ---------------- CSR build ----------------
__global__ void k_count(const int* __restrict__ ei){
    int e = blockIdx.x*blockDim.x + threadIdx.x;
    if(e<NE) atomicAdd(&g_cnt[ei[e]], 1);
}
__global__ void k_scan(){
    __shared__ int sh[1024];
    int t = threadIdx.x;
    int v0 = g_cnt[2*t], v1 = g_cnt[2*t+1];
    int s = v0+v1;
    sh[t]=s; __syncthreads();
    #pragma unroll
    for(int off=1; off<1024; off<<=1){
        int x = (t>=off)? sh[t-off] : 0;
        __syncthreads();
        sh[t] += x;
        __syncthreads();
    }
    int incl = sh[t];
    int excl = incl - s;
    g_row[2*t]   = excl;
    g_row[2*t+1] = excl + v0;
    if(t==1023) g_row[2048]=incl;
}
__global__ void k_place(const int* __restrict__ ei){
    int e = blockIdx.x*blockDim.x + threadIdx.x;
    if(e<NE){
        int s = ei[e];
        int p = atomicAdd(&g_cur[s],1);
        g_eord[g_row[s]+p] = e;
    }
}

// ---------------- node prep ----------------
__global__ void k_node_prep(const float* __restrict__ Xin){
    int idx = blockIdx.x*blockDim.x + threadIdx.x;
    if(idx>=NH) return;
    float t[9]; float nrm=0.f;
    #pragma unroll
    for(int r=0;r<9;r++){ t[r]=Xin[(size_t)idx*9+r]; nrm += t[r]*t[r]; }
    float inv = 1.f/(nrm+1.f);
    #pragma unroll
    for(int r=0;r<9;r++){ t[r]*=inv; g_Xn[(size_t)idx*9+r]=t[r]; }
    float c[9]; tocompact(t,1.f,c);
    #pragma unroll
    for(int d=0;d<9;d++) g_cA[d*NH+idx]=c[d];
}

// ---------------- channel mix on tensor cores: 64-node blocks ----------------
#define MIX_PADW 72
#define MIX_SMEMW (2*64*MIX_PADW)

__global__ void __launch_bounds__(256,4)
k_mix_mma(int which, int wbase){
    extern __shared__ u32 smu[];
    u32* inh = smu;
    u32* inl = smu + 64*MIX_PADW;
    const float* in  = which ? g_c2  : g_cA;
    float*       out = which ? g_dXc : g_cM;
    int d = blockIdx.y;
    int m = (d==0)?0:((d<4)?1:2);
    int lm = wbase + m;
    int nblk = blockIdx.x*64;
    int tid = threadIdx.x;
    int warp = tid>>5, lane = tid&31;
    int g = lane>>2, t = lane&3;
    int hw = warp;

    const float* src = in + (size_t)d*NH + (size_t)nblk*HH;
    for(int i=tid;i<2048;i+=256){
        int e=i>>5, k4=(i&31)<<2;
        float4 v = *(const float4*)&src[e*128 + k4];
        int kc = k4>>4;
        int lw = (k4&15)>>1;
        u32 hi0,lo0,hi1,lo1;
        split_pair(v.x,v.y,hi0,lo0);
        split_pair(v.z,v.w,hi1,lo1);
        int base = e*MIX_PADW + kc*8;
        inh[base + wpos(lw)]   = hi0;
        inh[base + wpos(lw+1)] = hi1;
        inl[base + wpos(lw)]   = lo0;
        inl[base + wpos(lw+1)] = lo1;
    }
    __syncthreads();

    const uint4* Wm = (const uint4*)(g_WmF + (size_t)lm*64*32*8);
    float dacc[1][8][4];
    #pragma unroll
    for(int nt=0;nt<8;nt++){ dacc[0][nt][0]=dacc[0][nt][1]=dacc[0][nt][2]=dacc[0][nt][3]=0.f; }
    WF wa[1], wb[1];
    ldwf(Wm, (hw*8+0)*32+lane, wa[0]);
    #pragma unroll 1
    for(int kc=0;kc<8;kc+=2){
        ldwf(Wm, (hw*8+kc+1)*32+lane, wb[0]);
        do_mma16_M<1>(dacc, wa, inh, inl, MIX_PADW, 0, kc*8, g, t);
        if(kc+2<8) ldwf(Wm, (hw*8+kc+2)*32+lane, wa[0]);
        do_mma16_M<1>(dacc, wb, inh, inl, MIX_PADW, 0, (kc+1)*8, g, t);
    }
    float* outp = out + (size_t)d*NH + (size_t)nblk*HH;
    int oA = hw*16 + g, oB = oA + 8;
    #pragma unroll
    for(int nt=0;nt<8;nt++){
        int e0 = nt*8 + 2*t;
        outp[e0*128 + oA]     = dacc[0][nt][0];
        outp[(e0+1)*128 + oA] = dacc[0][nt][1];
        outp[e0*128 + oB]     = dacc[0][nt][2];
        outp[(e0+1)*128 + oB] = dacc[0][nt][3];
    }
}

// ---------------- edge MLP: 64-edge blocks, 256 threads, 2 blocks/SM ----------
#define A_PADW  40
#define H1_PADW 72
#define H2_PADW 136
#define MLP_SMEMW (64 + 2*64*H1_PADW + 2*64*H2_PADW)

__global__ void __launch_bounds__(256,2)
k_mlp_mma(const float* __restrict__ attr, const float* __restrict__ ewt,
          const float* __restrict__ b1, const float* __restrict__ b2,
          const float* __restrict__ b3raw, int l){
    extern __shared__ u32 smu[];
    float* cv = (float*)smu;
    u32* h1h = smu + 64;
    u32* h1l = h1h + 64*H1_PADW;
    u32* h2h = h1l + 64*H1_PADW;
    u32* h2l = h2h + 64*H2_PADW;
    u32* aah = h2h;                    // attr planes alias h2 (stage-1 only)
    u32* aal = h2l;
    int tid = threadIdx.x;
    int warp = tid>>5, lane = tid&31;
    int g = lane>>2, t = lane&3;
    int hw = warp;                     // out-slice 0..7
    int eblk = blockIdx.x*64;

    const uint4* W1 = (const uint4*)(g_W1f + (size_t)l*4096);
    const uint4* W2 = (const uint4*)(g_W2f + (size_t)l*32768);
    const uint4* W3 = (const uint4*)(g_W3f + (size_t)l*98304);

    // stage attr into hi/lo planes (64 edges x 8 words)
    for(int i=tid;i<512;i+=256){
        int e=i>>3, k4=(i&7)<<2;
        float4 v = *(const float4*)&attr[(size_t)(eblk+e)*32 + k4];
        int kc = k4>>4;
        int lw = (k4&15)>>1;
        u32 hi0,lo0,hi1,lo1;
        split_pair(v.x,v.y,hi0,lo0);
        split_pair(v.z,v.w,hi1,lo1);
        int base = e*A_PADW + kc*8;
        aah[base + wpos(lw)]   = hi0;
        aah[base + wpos(lw+1)] = hi1;
        aal[base + wpos(lw)]   = lo0;
        aal[base + wpos(lw+1)] = lo1;
    }
    if(tid<64){
        float wv = ewt[eblk+tid];
        cv[tid] = (wv < CUT) ? 0.5f*(cosf(wv*(3.14159265358979f/CUT))+1.f) : 0.f;
    }
    __syncthreads();

    // ---- stage 1: 1 m-tile (outputs hw*16..+16), K=32 (2 chunks), 64 edges ----
    {
        float d[1][8][4];
        #pragma unroll
        for(int nt=0;nt<8;nt++){ d[0][nt][0]=d[0][nt][1]=d[0][nt][2]=d[0][nt][3]=0.f; }
        WF wa[1], wb[1];
        ldwf(W1, (hw*2+0)*32+lane, wa[0]);
        ldwf(W1, (hw*2+1)*32+lane, wb[0]);
        do_mma16_M<1>(d, wa, aah, aal, A_PADW, 0, 0, g, t);
        do_mma16_M<1>(d, wb, aah, aal, A_PADW, 0, 8, g, t);
        int o = hw*16;
        float bA=b1[o+g], bB=b1[o+g+8];
        #pragma unroll
        for(int nt=0;nt<8;nt++){
            int e = nt*8 + 2*t;
            st_hl(h1h,h1l,H1_PADW,e,  o+g,  siluf(d[0][nt][0]+bA));
            st_hl(h1h,h1l,H1_PADW,e+1,o+g,  siluf(d[0][nt][1]+bA));
            st_hl(h1h,h1l,H1_PADW,e,  o+g+8,siluf(d[0][nt][2]+bB));
            st_hl(h1h,h1l,H1_PADW,e+1,o+g+8,siluf(d[0][nt][3]+bB));
        }
    }
    __syncthreads();

    // ---- stage 2: single pass, 2 m-tiles (outputs hw*32..+32), K=128 ----
    {
        float d[2][8][4];
        #pragma unroll
        for(int m=0;m<2;m++)
            #pragma unroll
            for(int nt=0;nt<8;nt++){ d[m][nt][0]=d[m][nt][1]=d[m][nt][2]=d[m][nt][3]=0.f; }
        WF wa[2], wb[2];
        #pragma unroll
        for(int m=0;m<2;m++) ldwf(W2, ((hw*2+m)*8+0)*32+lane, wa[m]);
        #pragma unroll 1
        for(int kc=0;kc<8;kc+=2){
            #pragma unroll
            for(int m=0;m<2;m++) ldwf(W2, ((hw*2+m)*8+kc+1)*32+lane, wb[m]);
            do_mma16_M<2>(d, wa, h1h, h1l, H1_PADW, 0, kc*8, g, t);
            if(kc+2<8){
                #pragma unroll
                for(int m=0;m<2;m++) ldwf(W2, ((hw*2+m)*8+kc+2)*32+lane, wa[m]);
            }
            do_mma16_M<2>(d, wb, h1h, h1l, H1_PADW, 0, (kc+1)*8, g, t);
        }
        #pragma unroll
        for(int m=0;m<2;m++){
            int oo = hw*32 + m*16;
            float bA=b2[oo+g], bB=b2[oo+g+8];
            #pragma unroll
            for(int nt=0;nt<8;nt++){
                int e = nt*8 + 2*t;
                st_hl(h2h,h2l,H2_PADW,e,  oo+g,  siluf(d[m][nt][0]+bA));
                st_hl(h2h,h2l,H2_PADW,e+1,oo+g,  siluf(d[m][nt][1]+bA));
                st_hl(h2h,h2l,H2_PADW,e,  oo+g+8,siluf(d[m][nt][2]+bB));
                st_hl(h2h,h2l,H2_PADW,e+1,oo+g+8,siluf(d[m][nt][3]+bB));
            }
        }
    }
    __syncthreads();

    // ---- stage 3: pass A = 2 m-tiles, pass B = 1 m-tile (outputs hw*48..+48) ----
    {
        float d[2][8][4];
        #pragma unroll
        for(int m=0;m<2;m++)
            #pragma unroll
            for(int nt=0;nt<8;nt++){ d[m][nt][0]=d[m][nt][1]=d[m][nt][2]=d[m][nt][3]=0.f; }
        WF wa[2], wb[2];
        #pragma unroll
        for(int m=0;m<2;m++) ldwf(W3, ((hw*3+m)*16+0)*32+lane, wa[m]);
        #pragma unroll 1
        for(int kc=0;kc<16;kc+=2){
            #pragma unroll
            for(int m=0;m<2;m++) ldwf(W3, ((hw*3+m)*16+kc+1)*32+lane, wb[m]);
            do_mma16_M<2>(d, wa, h2h, h2l, H2_PADW, 0, kc*8, g, t);
            if(kc+2<16){
                #pragma unroll
                for(int m=0;m<2;m++) ldwf(W3, ((hw*3+m)*16+kc+2)*32+lane, wa[m]);
            }
            do_mma16_M<2>(d, wb, h2h, h2l, H2_PADW, 0, (kc+1)*8, g, t);
        }
        #pragma unroll
        for(int m=0;m<2;m++){
            int oA = hw*48 + m*16 + g, oB = oA + 8;
            float bA = b3raw[(oA&127)*3 + (oA>>7)];
            float bB = b3raw[(oB&127)*3 + (oB>>7)];
            #pragma unroll
            for(int nt=0;nt<8;nt++){
                int e0 = nt*8 + 2*t;
                float c0 = cv[e0], c1 = cv[e0+1];
                float* ep0 = g_ea + (size_t)(eblk+e0)*384;
                float* ep1 = g_ea + (size_t)(eblk+e0+1)*384;
                ep0[oA] = siluf(d[m][nt][0]+bA)*c0;
                ep1[oA] = siluf(d[m][nt][1]+bA)*c1;
                ep0[oB] = siluf(d[m][nt][2]+bB)*c0;
                ep1[oB] = siluf(d[m][nt][3]+bB)*c1;
            }
        }
    }
    {
        float d[1][8][4];
        #pragma unroll
        for(int nt=0;nt<8;nt++){ d[0][nt][0]=d[0][nt][1]=d[0][nt][2]=d[0][nt][3]=0.f; }
        WF wa[1], wb[1];
        ldwf(W3, ((hw*3+2)*16+0)*32+lane, wa[0]);
        #pragma unroll 1
        for(int kc=0;kc<16;kc+=2){
            ldwf(W3, ((hw*3+2)*16+kc+1)*32+lane, wb[0]);
            do_mma16_M<1>(d, wa, h2h, h2l, H2_PADW, 0, kc*8, g, t);
            if(kc+2<16) ldwf(W3, ((hw*3+2)*16+kc+2)*32+lane, wa[0]);
            do_mma16_M<1>(d, wb, h2h, h2l, H2_PADW, 0, (kc+1)*8, g, t);
        }
        int oA = hw*48 + 2*16 + g, oB = oA + 8;
        float bA = b3raw[(oA&127)*3 + (oA>>7)];
        float bB = b3raw[(oB&127)*3 + (oB>>7)];
        #pragma unroll
        for(int nt=0;nt<8;nt++){
            int e0 = nt*8 + 2*t;
            float c0 = cv[e0], c1 = cv[e0+1];
            float* ep0 = g_ea + (size_t)(eblk+e0)*384;
            float* ep1 = g_ea + (size_t)(eblk+e0+1)*384;
            ep0[oA] = siluf(d[0][nt][0]+bA)*c0;
            ep1[oA] = siluf(d[0][nt][1]+bA)*c1;
            ep0[oB] = siluf(d[0][nt][2]+bB)*c0;
            ep1[oB] = siluf(d[0][nt][3]+bB)*c1;
        }
    }
}

// ---------------- gather segment-sum + O(3) node update ----------------
__global__ void __launch_bounds__(128) k_gather_update(const int* __restrict__ ei,
                                                       const float* __restrict__ q){
    int n = blockIdx.x;
    int h = threadIdx.x;
    int s = g_row[n], e1 = g_row[n+1];
    float cm[9];
    #pragma unroll
    for(int d=0;d<9;d++) cm[d]=0.f;
    for(int t=s;t<e1;t++){
        int e = g_eord[t];
        int dst = ei[NE + e];
        const float* ep = g_ea + (size_t)e*384;
        float a0=ep[h], a1=ep[128+h], a2=ep[256+h];
        int di = dst*HH + h;
        cm[0] += a0*g_cM[0*NH+di];
        cm[1] += a1*g_cM[1*NH+di];
        cm[2] += a1*g_cM[2*NH+di];
        cm[3] += a1*g_cM[3*NH+di];
        cm[4] += a2*g_cM[4*NH+di];
        cm[5] += a2*g_cM[5*NH+di];
        cm[6] += a2*g_cM[6*NH+di];
        cm[7] += a2*g_cM[7*NH+di];
        cm[8] += a2*g_cM[8*NH+di];
    }
    int idx = n*HH + h;
    float cy[9];
    #pragma unroll
    for(int d=0;d<9;d++) cy[d]=g_cM[d*NH+idx];
    float M[9], Y[9];
    rec(cm,M); rec(cy,Y);
    float AB[9];
    #pragma unroll
    for(int r=0;r<9;r++) AB[r]=0.f;
    mmadd(M,Y,AB); mmadd(Y,M,AB);
    float f = 1.f + 0.1f*q[n];
    float T[9]; float nrm=0.f;
    #pragma unroll
    for(int r=0;r<9;r++){ T[r]=f*AB[r]; nrm += T[r]*T[r]; }
    float inv = 1.f/(nrm+1.f);
    float c2[9]; tocompact(T,inv,c2);
    #pragma unroll
    for(int d=0;d<9;d++) g_c2[d*NH+idx]=c2[d];
}

// ---------------- final node update ----------------
__global__ void k_upd_b(const float* __restrict__ q, float* __restrict__ Xout){
    int idx = blockIdx.x*blockDim.x + threadIdx.x;
    if(idx>=NH) return;
    float c[9];
    #pragma unroll
    for(int d=0;d<9;d++) c[d]=g_dXc[d*NH+idx];
    float dx[9]; rec(c,dx);
    float f = 1.f + 0.1f*q[idx>>7];
    float D2[9];
    #pragma unroll
    for(int r=0;r<9;r++) D2[r]=0.f;
    mmadd(dx,dx,D2);
    #pragma unroll
    for(int r=0;r<9;r++)
        Xout[(size_t)idx*9+r] = g_Xn[(size_t)idx*9+r] + dx[r] + f*D2[r];
}

// ---------------- launcher (k_mlp_mma at index 3 for ncu) ----------------------
extern "C" void kernel_launch(void* const* d_in, const int* in_sizes, int n_in,
                              void* d_out, int out_size){
    const float* X    = (const float*)d_in[0];
    const float* attr = (const float*)d_in[1];
    const float* ewt  = (const float*)d_in[2];
    const float* q    = (const float*)d_in[3];
    const float* Ws1  = (const float*)d_in[4];
    const float* bs1  = (const float*)d_in[5];
    const float* Ws2  = (const float*)d_in[6];
    const float* bs2  = (const float*)d_in[7];
    const float* Ws3  = (const float*)d_in[8];
    const float* bs3  = (const float*)d_in[9];
    const float* Wt   = (const float*)d_in[10];
    const int*   ei   = (const int*)d_in[11];
    float* out = (float*)d_out;

    cudaFuncSetAttribute(k_mlp_mma, cudaFuncAttributeMaxDynamicSharedMemorySize,
                         MLP_SMEMW*4);
    cudaFuncSetAttribute(k_mix_mma, cudaFuncAttributeMaxDynamicSharedMemorySize,
                         MIX_SMEMW*4);

    k_prep_w<<<264,256>>>(Ws1,Ws2,Ws3,Wt);                                   // 0 (+zero cnt)
    k_node_prep<<<NH/256,256>>>(X);                                          // 1
    k_count<<<NE/256,256>>>(ei);                                             // 2
    k_mlp_mma<<<NE/64,256,MLP_SMEMW*4>>>(attr, ewt, bs1, bs2, bs3, 0);       // 3 <- ncu
    k_mix_mma<<<dim3(32,9),256,MIX_SMEMW*4>>>(0, 0);                         // 4
    k_scan<<<1,1024>>>();                                                    // 5
    k_place<<<NE/256,256>>>(ei);                                             // 6
    k_gather_update<<<NA,128>>>(ei, q);                                      // 7
    k_mix_mma<<<dim3(32,9),256,MIX_SMEMW*4>>>(1, 3);                         // 8
    k_upd_b<<<NH/256,256>>>(q, out);                                         // 9

    // layer 1 (CSR already built)
    k_node_prep<<<NH/256,256>>>(out);
    k_mix_mma<<<dim3(32,9),256,MIX_SMEMW*4>>>(0, 6);
    k_mlp_mma<<<NE/64,256,MLP_SMEMW*4>>>(attr, ewt, bs1+128, bs2+256, bs3+384, 1);
    k_gather_update<<<NA,128>>>(ei, q);
    k_mix_mma<<<dim3(32,9),256,MIX_SMEMW*4>>>(1, 9);
    k_upd_b<<<NH/256,256>>>(q, out);
}